// round 16
// baseline (speedup 1.0000x reference)
#include <cuda_runtime.h>

// Problem constants
#define Bsz 512
#define Tn  2048
#define Dn  64
#define Hn  66
#define Gn  264            // 4*H
#define RPB 4              // batch rows per block (loop kernel)
#define NBLK (Bsz / RPB)   // 128 blocks

// Loop kernel: thread = (feature j, gate q, K-split s): tid = j*8 + q*2 + s
#define HP   80            // H padded 66 -> 80 (16B-aligned K-splits)
#define KCL  40            // K-chunk per split (HP/2); s*160B -> 16B aligned
#define NFL  68            // padded features
#define LNT  (NFL * 4 * 2) // 544 threads = 17 warps

typedef unsigned long long ull;

// Inter-kernel scratch
__device__ float g_xp[Bsz * Tn * Gn];   // x @ W_ih^T + b_ih + b_hh   (1.1 GB)
__device__ float g_hT[Bsz * Hn];
__device__ float g_wp[Hn];
__device__ float g_pc[Hn];

// ---- packed f32x2 helpers (Blackwell) ----
__device__ __forceinline__ ull fma2(ull a, ull b, ull c) {
    ull d;
    asm("fma.rn.f32x2 %0, %1, %2, %3;" : "=l"(d) : "l"(a), "l"(b), "l"(c));
    return d;
}
__device__ __forceinline__ float hadd2(ull a) {
    float x, y;
    asm("mov.b64 {%0, %1}, %2;" : "=f"(x), "=f"(y) : "l"(a));
    return x + y;
}
__device__ __forceinline__ ull pack2(float a, float b) {
    ull r;
    asm("mov.b64 %0, {%1, %2};" : "=l"(r) : "f"(a), "f"(b));
    return r;
}

__device__ __forceinline__ float sigf(float x) {
    return 1.0f / (1.0f + __expf(-x));
}
__device__ __forceinline__ float tanh_fast(float x) {
    float e = __expf(-2.0f * fabsf(x));
    float r = (1.0f - e) / (1.0f + e);
    return copysignf(r, x);
}
__device__ __forceinline__ float sel4(int m, float v0, float v1, float v2, float v3) {
    return m == 0 ? v0 : (m == 1 ? v1 : (m == 2 ? v2 : v3));
}

// ============================================================================
// Phase 1: xproj[b][t][g] = x[b][t][:] @ W_ih[g][:] + b_ih[g] + b_hh[g]
// One block = 32 (b,t) rows x all 264 gates. Weights in registers (32 pairs).
// ============================================================================
#define P1_ROWS 32
#define P1_THR  288

__global__ void __launch_bounds__(P1_THR, 2) xproj_kernel(
    const float* __restrict__ x,
    const float* __restrict__ W_ih,
    const float* __restrict__ b_ih,
    const float* __restrict__ b_hh)
{
    __shared__ __align__(16) float xt[P1_ROWS][Dn];   // 8 KB
    const int tid = threadIdx.x;
    const int bt0 = blockIdx.x * P1_ROWS;             // Tn % 32 == 0: tile within one b

    // load x tile (coalesced float4)
    {
        const float4* src = (const float4*)(x + (size_t)bt0 * Dn);
        float4* dst = (float4*)&xt[0][0];
        for (int i = tid; i < P1_ROWS * Dn / 4; i += P1_THR) dst[i] = src[i];
    }

    const int g = tid;                 // gate row; active for g < 264
    const bool act = (g < Gn);
    ull w[Dn / 2];
    float bz = 0.0f;
    #pragma unroll
    for (int kk = 0; kk < Dn / 2; ++kk) w[kk] = 0ull;
    if (act) {
        #pragma unroll
        for (int kk = 0; kk < Dn / 2; ++kk)
            w[kk] = pack2(W_ih[g * Dn + 2 * kk], W_ih[g * Dn + 2 * kk + 1]);
        bz = b_ih[g] + b_hh[g];
    }
    __syncthreads();

    #pragma unroll
    for (int rg = 0; rg < P1_ROWS / 4; ++rg) {
        ull a0 = 0, a1 = 0, a2 = 0, a3 = 0;
        #pragma unroll
        for (int k4 = 0; k4 < Dn / 4; ++k4) {
            ulonglong2 V0 = *(const ulonglong2*)&xt[rg * 4 + 0][4 * k4];
            ulonglong2 V1 = *(const ulonglong2*)&xt[rg * 4 + 1][4 * k4];
            ulonglong2 V2 = *(const ulonglong2*)&xt[rg * 4 + 2][4 * k4];
            ulonglong2 V3 = *(const ulonglong2*)&xt[rg * 4 + 3][4 * k4];
            a0 = fma2(w[2 * k4], V0.x, a0); a0 = fma2(w[2 * k4 + 1], V0.y, a0);
            a1 = fma2(w[2 * k4], V1.x, a1); a1 = fma2(w[2 * k4 + 1], V1.y, a1);
            a2 = fma2(w[2 * k4], V2.x, a2); a2 = fma2(w[2 * k4 + 1], V2.y, a2);
            a3 = fma2(w[2 * k4], V3.x, a3); a3 = fma2(w[2 * k4 + 1], V3.y, a3);
        }
        if (act) {
            g_xp[(size_t)(bt0 + rg * 4 + 0) * Gn + g] = hadd2(a0) + bz;
            g_xp[(size_t)(bt0 + rg * 4 + 1) * Gn + g] = hadd2(a1) + bz;
            g_xp[(size_t)(bt0 + rg * 4 + 2) * Gn + g] = hadd2(a2) + bz;
            g_xp[(size_t)(bt0 + rg * 4 + 3) * Gn + g] = hadd2(a3) + bz;
        }
    }
}

// ============================================================================
// Phase 2: recurrence.  gates = xp[t] + h @ W_hh^T  (W_hh in registers)
// ============================================================================
__global__ void __launch_bounds__(LNT, 1) lstm_loop_kernel(
    const float* __restrict__ W_hh)   // [4H, H]
{
    __shared__ __align__(16) float v_s[2 * RPB * HP];  // double-buffered h (padded)

    const int tid  = threadIdx.x;
    const int row0 = blockIdx.x * RPB;

    const int j = tid >> 3;          // feature 0..67 (66,67 pad)
    const int q = (tid >> 1) & 3;    // gate 0..3 (i,f,g,o)
    const int s = tid & 1;           // K-split
    const int kb = s * KCL;          // float offset; s*160B -> 16B aligned
    const bool valid = (j < Hn);
    const int grow = q * Hn + (valid ? j : 0);

    // zero h buffers (pad region stays 0 forever)
    for (int i = tid; i < 2 * RPB * HP; i += LNT) v_s[i] = 0.0f;

    // W_hh chunk -> 20 ull regs (zeros beyond H=66 / for pad threads)
    ull w[KCL / 2];
    #pragma unroll
    for (int kk = 0; kk < KCL / 2; ++kk) {
        const int k = kb + 2 * kk;
        float a = (valid && k     < Hn) ? W_hh[grow * Hn + k]     : 0.0f;
        float b = (valid && k + 1 < Hn) ? W_hh[grow * Hn + k + 1] : 0.0f;
        w[kk] = pack2(a, b);
    }

    // xp prefetch for t=0: this thread consumes rows s and s+2, gate grow
    float xpA = 0.0f, xpB = 0.0f;
    if (valid) {
        xpA = g_xp[(size_t)((row0 + s)     * Tn + 0) * Gn + grow];
        xpB = g_xp[(size_t)((row0 + s + 2) * Tn + 0) * Gn + grow];
    }
    __syncthreads();

    float cA = 0.0f, cB = 0.0f, hA = 0.0f, hB = 0.0f;
    int buf = 0;

    for (int t = 0; t < Tn; ++t) {
        // prefetch xp for t+1 (hidden under the FMA phase)
        float xnA = 0.0f, xnB = 0.0f;
        if (valid && t + 1 < Tn) {
            xnA = g_xp[(size_t)((row0 + s)     * Tn + t + 1) * Gn + grow];
            xnB = g_xp[(size_t)((row0 + s + 2) * Tn + t + 1) * Gn + grow];
        }

        const float* vb = v_s + buf * (RPB * HP);

        // ---- recurrent partials: 10 x {4 LDS.128 + 8 fma2} ----
        ull a0 = 0, a1 = 0, a2 = 0, a3 = 0;
        #pragma unroll
        for (int k4 = 0; k4 < KCL / 4; ++k4) {
            ulonglong2 V0 = *(const ulonglong2*)(vb + 0 * HP + kb + 4 * k4);
            ulonglong2 V1 = *(const ulonglong2*)(vb + 1 * HP + kb + 4 * k4);
            ulonglong2 V2 = *(const ulonglong2*)(vb + 2 * HP + kb + 4 * k4);
            ulonglong2 V3 = *(const ulonglong2*)(vb + 3 * HP + kb + 4 * k4);
            a0 = fma2(w[2 * k4], V0.x, a0); a0 = fma2(w[2 * k4 + 1], V0.y, a0);
            a1 = fma2(w[2 * k4], V1.x, a1); a1 = fma2(w[2 * k4 + 1], V1.y, a1);
            a2 = fma2(w[2 * k4], V2.x, a2); a2 = fma2(w[2 * k4 + 1], V2.y, a2);
            a3 = fma2(w[2 * k4], V3.x, a3); a3 = fma2(w[2 * k4 + 1], V3.y, a3);
        }
        float f0 = hadd2(a0), f1 = hadd2(a1), f2 = hadd2(a2), f3 = hadd2(a3);

        // ---- K-split reduction (xor 1): lane s keeps rows {s, s+2} ----
        float sa = s ? f0 : f1;                 // rows I discard
        float sb = s ? f2 : f3;
        float A = (s ? f1 : f0) + __shfl_xor_sync(0xffffffffu, sa, 1); // row s
        float B = (s ? f3 : f2) + __shfl_xor_sync(0xffffffffu, sb, 1); // row s+2
        A += xpA;                                // xproj already includes biases
        B += xpB;

        // ---- gate gather across q (xor 2, xor 4): Vm = gate q^m ----
        float A1 = __shfl_xor_sync(0xffffffffu, A, 2);
        float A2 = __shfl_xor_sync(0xffffffffu, A, 4);
        float A3 = __shfl_xor_sync(0xffffffffu, A1, 4);
        float B1 = __shfl_xor_sync(0xffffffffu, B, 2);
        float B2 = __shfl_xor_sync(0xffffffffu, B, 4);
        float B3 = __shfl_xor_sync(0xffffffffu, B1, 4);

        float GiA = sel4(q,     A, A1, A2, A3);
        float GfA = sel4(q ^ 1, A, A1, A2, A3);
        float GgA = sel4(q ^ 2, A, A1, A2, A3);
        float GoA = sel4(q ^ 3, A, A1, A2, A3);
        float GiB = sel4(q,     B, B1, B2, B3);
        float GfB = sel4(q ^ 1, B, B1, B2, B3);
        float GgB = sel4(q ^ 2, B, B1, B2, B3);
        float GoB = sel4(q ^ 3, B, B1, B2, B3);

        // ---- pointwise (redundant over q; MUFU overlaps other warps' FMA) ----
        cA = sigf(GfA) * cA + sigf(GiA) * tanh_fast(GgA);
        hA = sigf(GoA) * tanh_fast(cA);
        cB = sigf(GfB) * cB + sigf(GiB) * tanh_fast(GgB);
        hB = sigf(GoB) * tanh_fast(cB);

        // ---- write h to next buffer (q==0 lanes), rotate ----
        float* vn = v_s + (buf ^ 1) * (RPB * HP);
        if (valid && q == 0) {
            vn[s * HP + j]       = hA;
            vn[(s + 2) * HP + j] = hB;
        }
        xpA = xnA; xpB = xnB;
        buf ^= 1;
        __syncthreads();   // the ONE barrier per step
    }

    if (valid && q == 0) {
        g_hT[(row0 + s)     * Hn + j] = hA;
        g_hT[(row0 + s + 2) * Hn + j] = hB;
    }
}

// ---- BN stats + folded FC weights: one block per feature ----
__global__ void bn_stats_kernel(
    const float* __restrict__ gamma,
    const float* __restrict__ beta,
    const float* __restrict__ fcw)
{
    __shared__ float sm[64], sm2[64];
    const int f   = blockIdx.x;   // 0..65
    const int tid = threadIdx.x;  // 64 threads

    float s = 0.0f, sq = 0.0f;
    for (int b = tid; b < Bsz; b += 64) {
        float v = g_hT[b * Hn + f];
        s += v; sq += v * v;
    }
    sm[tid] = s; sm2[tid] = sq;
    __syncthreads();
    for (int o = 32; o > 0; o >>= 1) {
        if (tid < o) { sm[tid] += sm[tid + o]; sm2[tid] += sm2[tid + o]; }
        __syncthreads();
    }
    if (tid == 0) {
        float mean = sm[0] * (1.0f / Bsz);
        float var  = sm2[0] * (1.0f / Bsz) - mean * mean;  // biased (jnp.var)
        float rs   = rsqrtf(var + 1e-5f);
        float wv   = gamma[f] * rs * fcw[f];
        g_wp[f] = wv;
        g_pc[f] = beta[f] * fcw[f] - mean * wv;
    }
}

// logits[b] = fc_b + sum_j pc[j] + sum_j hT[b][j]*wp[j]
__global__ void fc_kernel(const float* __restrict__ fcb, float* __restrict__ out)
{
    const int b = blockIdx.x * blockDim.x + threadIdx.x;
    if (b >= Bsz) return;
    float acc = fcb[0];
    #pragma unroll
    for (int j = 0; j < Hn; ++j) acc += g_pc[j];
    #pragma unroll
    for (int j = 0; j < Hn; ++j) acc += g_hT[b * Hn + j] * g_wp[j];
    out[b] = acc;
}

extern "C" void kernel_launch(void* const* d_in, const int* in_sizes, int n_in,
                              void* d_out, int out_size)
{
    const float* x     = (const float*)d_in[0];
    const float* W_ih  = (const float*)d_in[1];
    const float* W_hh  = (const float*)d_in[2];
    const float* b_ih  = (const float*)d_in[3];
    const float* b_hh  = (const float*)d_in[4];
    const float* gamma = (const float*)d_in[5];
    const float* beta  = (const float*)d_in[6];
    const float* fcw   = (const float*)d_in[7];
    const float* fcb   = (const float*)d_in[8];

    xproj_kernel<<<(Bsz * Tn) / P1_ROWS, P1_THR>>>(x, W_ih, b_ih, b_hh);
    lstm_loop_kernel<<<NBLK, LNT>>>(W_hh);
    bn_stats_kernel<<<Hn, 64>>>(gamma, beta, fcw);
    fc_kernel<<<2, 256>>>(fcb, (float*)d_out);
}